// round 16
// baseline (speedup 1.0000x reference)
#include <cuda_runtime.h>

// Shapes fixed by the problem: bz=4, C=32, H=W=256, NF=12 focal slices.
#define NF    12
#define BZ    4
#define C_    32
#define HW    65536           // 256*256
#define CHW   (C_ * HW)       // 2,097,152
#define CHW4  (CHW / 4)       // 524,288 = 2^19
#define HW4   (HW / 4)        // 16,384

#define BPB   128             // reduction blocks along the chunk axis (R2-exact)
#define TPB   256
#define CHUNK (CHW4 / BPB)    // 4096 float4 per block (16 iters/thread)

// Scratch (no allocation allowed).
__device__ float g_part[BZ * NF * BPB];   // 24 KB -> L2-resident for k_select
__device__ int   g_sel[2 * BZ];           // [0..BZ) = i, [BZ..2BZ) = j per batch

// ---------------------------------------------------------------------------
// Kernel 1: R2-exact reduce structure; xf loads now DEFAULT eviction policy so
// the L2 tail (~120MB of the freshest streamed data) survives for k_copy.
// Each block owns one (b, chunk), accumulates ALL 12 focal MAEs.
// grid = (BPB, BZ).
// ---------------------------------------------------------------------------
__global__ __launch_bounds__(TPB, 2) void k_reduce(const float* __restrict__ x,
                                                   const float* __restrict__ xf,
                                                   const float* __restrict__ sal) {
    const int b    = blockIdx.y;
    const int base = blockIdx.x * CHUNK;

    const float4* __restrict__ xp = (const float4*)(x   + (size_t)b * CHW);
    const float4* __restrict__ sp = (const float4*)(sal + (size_t)b * HW);

    const float4* __restrict__ fp[NF];
#pragma unroll
    for (int f = 0; f < NF; ++f)
        fp[f] = (const float4*)(xf + ((size_t)f * BZ + b) * CHW);

    float acc[NF];
#pragma unroll
    for (int f = 0; f < NF; ++f) acc[f] = 0.f;

    for (int i = threadIdx.x; i < CHUNK; i += TPB) {
        const int v = base + i;
        const float4 a = xp[v];
        const float4 s = sp[v & (HW4 - 1)];       // sal broadcast over channels
        float4 g[NF];
#pragma unroll
        for (int f = 0; f < NF; ++f) g[f] = __ldg(&fp[f][v]);   // evict-normal
#pragma unroll
        for (int f = 0; f < NF; ++f) {
            acc[f] += fabsf(s.x * (a.x - g[f].x));
            acc[f] += fabsf(s.y * (a.y - g[f].y));
            acc[f] += fabsf(s.z * (a.z - g[f].z));
            acc[f] += fabsf(s.w * (a.w - g[f].w));
        }
    }

    // Warp shuffle reduce each of the 12 accumulators, then combine warps.
    const int lane = threadIdx.x & 31;
    const int warp = threadIdx.x >> 5;
#pragma unroll
    for (int f = 0; f < NF; ++f) {
        float v = acc[f];
#pragma unroll
        for (int o = 16; o > 0; o >>= 1)
            v += __shfl_down_sync(0xffffffffu, v, o);
        acc[f] = v;   // valid on lane 0
    }

    __shared__ float sh[TPB / 32][NF];
    if (lane == 0) {
#pragma unroll
        for (int f = 0; f < NF; ++f) sh[warp][f] = acc[f];
    }
    __syncthreads();
    if (threadIdx.x < NF) {
        const int f = threadIdx.x;
        float s = 0.f;
#pragma unroll
        for (int w = 0; w < TPB / 32; ++w) s += sh[w][f];
        g_part[(b * NF + f) * BPB + blockIdx.x] = s;
    }
}

// ---------------------------------------------------------------------------
// Kernel 2: tiny standalone selection. PDL-gated on k_reduce's output.
// ---------------------------------------------------------------------------
__global__ void k_select() {
#if __CUDA_ARCH__ >= 900
    cudaGridDependencySynchronize();   // wait for k_reduce's g_part writes
#endif
    __shared__ double part4[BZ * NF][4];
    __shared__ double mae[BZ * NF];
    const int t = threadIdx.x;

    if (t < BZ * NF * 4) {
        const int bf = t >> 2;
        const int g  = t & 3;
        const float* __restrict__ row = &g_part[bf * BPB + g * 32];
        double s = 0.0;
#pragma unroll 8
        for (int q = 0; q < 32; ++q)             // batched -> MLP 8
            s += (double)__ldg(&row[q]);
        part4[bf][g] = s;
    }
    __syncthreads();
    if (t < BZ * NF)
        mae[t] = ((part4[t][0] + part4[t][1]) + part4[t][2]) + part4[t][3];
    __syncthreads();
    if (t < BZ) {
        double m[NF];
#pragma unroll
        for (int f = 0; f < NF; ++f) m[f] = mae[t * NF + f];
        double best = -1.0;
        int bi = 0, bj = 0;
        for (int i = 0; i < NF; ++i)
            for (int j = i + 1; j < NF; ++j) {
                const double d = m[i] - m[j];
                const double v = d * d;          // 0.5 irrelevant for ordering
                if (v > best) { best = v; bi = i; bj = j; }
            }
        if (!(best > 0.0)) { bi = 0; bj = 0; }
        g_sel[t]      = bi;
        g_sel[BZ + t] = bj;
    }
#if __CUDA_ARCH__ >= 900
    cudaTriggerProgrammaticLaunchCompletion();
#endif
}

// ---------------------------------------------------------------------------
// Kernel 3: gather-copy, PDL-gated on g_sel. Loads via __ldg (cache-all) to
// harvest L2 hits on the reduce's freshly-streamed tail. Batch 8 loads, then
// 8 write-back stores. Block chunk = 2048 float4 -> one output row per block.
// ---------------------------------------------------------------------------
#define CPT 8
__global__ __launch_bounds__(TPB) void k_copy(const float* __restrict__ xf,
                                              float* __restrict__ out) {
    const long long q0 = (long long)blockIdx.x * (TPB * CPT);
    const int r     = (int)(q0 >> 19);      // output row 0..7, constant per block
    const int b     = r & (BZ - 1);
    const int which = r >> 2;

#if __CUDA_ARCH__ >= 900
    cudaGridDependencySynchronize();   // wait for k_select's g_sel writes
#endif
    const int f = g_sel[which * BZ + b];

    const float4* __restrict__ src = (const float4*)(xf + ((size_t)f * BZ + b) * CHW);
    float4* __restrict__ dst = (float4*)out;

    const int n0 = (int)(q0 & (CHW4 - 1)) + threadIdx.x;
    float4 v[CPT];
#pragma unroll
    for (int c = 0; c < CPT; ++c) v[c] = __ldg(&src[n0 + c * TPB]);
#pragma unroll
    for (int c = 0; c < CPT; ++c) dst[q0 + threadIdx.x + c * TPB] = v[c];
}

// ---------------------------------------------------------------------------
// Launch: three kernels chained with Programmatic Dependent Launch.
// ---------------------------------------------------------------------------
static void launch_pdl(const void* func, dim3 grid, dim3 block, void** args) {
    cudaLaunchConfig_t cfg = {};
    cfg.gridDim  = grid;
    cfg.blockDim = block;
    cfg.dynamicSmemBytes = 0;
    cfg.stream = 0;
    cudaLaunchAttribute attr[1];
    attr[0].id = cudaLaunchAttributeProgrammaticStreamSerialization;
    attr[0].val.programmaticStreamSerializationAllowed = 1;
    cfg.attrs = attr;
    cfg.numAttrs = 1;
    cudaLaunchKernelExC(&cfg, func, args);
}

extern "C" void kernel_launch(void* const* d_in, const int* in_sizes, int n_in,
                              void* d_out, int out_size) {
    const float* x   = (const float*)d_in[0];   // [4,32,256,256]
    const float* xf  = (const float*)d_in[1];   // [48,32,256,256]
    const float* sal = (const float*)d_in[2];   // [4,1,256,256]
    float*       out = (float*)d_out;           // [8,32,256,256]

    dim3 gridR(BPB, BZ);
    k_reduce<<<gridR, TPB>>>(x, xf, sal);

    {   // k_select with PDL on k_reduce
        void* args[] = {};
        launch_pdl((const void*)k_select, dim3(1), dim3(192), args);
    }
    {   // k_copy with PDL on k_select
        const unsigned blocksC = (unsigned)((2LL * BZ * CHW4) / (TPB * CPT)); // 2048
        void* a0 = (void*)xf; void* a1 = (void*)out;
        void* args[] = {&a0, &a1};
        launch_pdl((const void*)k_copy, dim3(blocksC), dim3(TPB), args);
    }
}